// round 11
// baseline (speedup 1.0000x reference)
#include <cuda_runtime.h>
#include <cuda_fp16.h>
#include <cstdint>
#include <cstddef>

// Problem constants (fixed by the reference)
#define BB   2
#define NN   50000
#define EE   150000
#define FF   256
#define OUTD 256
#define RR   (BB * NN)       // 100000 rows
#define KTOT (3 * FF)        // 768
#define SEG  (4 * NN)        // 200000 segments
#define TOTE (4 * EE)        // 600000 CSR entries

#define NKB1 (KTOT / 16)     // 48 k-bricks for W1
#define NKB2 (256 / 16)      // 16 k-bricks for W2
#define NBLK ((RR + 127) / 128)   // 782 row panels

// ---------------------------------------------------------------------------
// Tiled activation layout (phase-1 A operand):
//   half (row r, k) -> g_a_t[ ((r>>7)*48 + (k>>4)) * 3072 + (r&127)*24 + (k&15) ]
// i.e. panel p, k-tile kt block = 128 rows x 24 halves (holes at 16..23) =
// 6144 B contiguous == one cp.async.bulk stage. kt 0..31 = agg, 32..47 = X.
// ---------------------------------------------------------------------------
#define KT_STRIDE_H 3072                       // halves per (panel, kt) block
#define PANEL_H     ((size_t)48 * KT_STRIDE_H) // 147456 halves per panel
__device__ __half g_a_t[(size_t)NBLK * PANEL_H];   // ~230 MB
__device__ __half g_x_h[(size_t)RR * 256];         // contiguous X fp16 (gather src)

// Fragment-packed weights (R10 layout): brick (nb, kb) = 32 lanes x 8 B.
__device__ __half g_w1p[32 * NKB1 * 128];
__device__ __half g_w2p[32 * NKB2 * 128];

// CSR scratch (self-cleaning across calls)
__device__ int   g_count[SEG];
__device__ int   g_fill[SEG];
__device__ int   g_start[SEG];
__device__ int2  g_entry[TOTE];

#define SCAN_TILE 2048
#define SCAN_NB   ((SEG + SCAN_TILE - 1) / SCAN_TILE)   // 98
__device__ volatile int g_scan_state[SCAN_NB];
__device__ int g_scan_agg[SCAN_NB];
__device__ int g_scan_incl[SCAN_NB];

// ---------------------------------------------------------------------------
// helpers
// ---------------------------------------------------------------------------
__device__ __forceinline__ float tanh_approx(float x) {
    float y;
    asm("tanh.approx.f32 %0, %1;" : "=f"(y) : "f"(x));
    return y;
}
__device__ __forceinline__ uint32_t pack_h2(float lo, float hi) {
    __half2 h = __floats2half2_rn(lo, hi);
    return *reinterpret_cast<uint32_t*>(&h);
}
__device__ __forceinline__ void mma_f16(float c[4],
                                        uint32_t a0, uint32_t a1, uint32_t a2, uint32_t a3,
                                        uint32_t b0, uint32_t b1) {
    asm volatile(
        "mma.sync.aligned.m16n8k16.row.col.f32.f16.f16.f32 "
        "{%0,%1,%2,%3}, {%4,%5,%6,%7}, {%8,%9}, {%0,%1,%2,%3};"
        : "+f"(c[0]), "+f"(c[1]), "+f"(c[2]), "+f"(c[3])
        : "r"(a0), "r"(a1), "r"(a2), "r"(a3), "r"(b0), "r"(b1));
}

#define MBARRIER_INIT(addr, cnt) \
    asm volatile("mbarrier.init.shared.b64 [%0], %1;" :: "r"(addr), "r"((uint32_t)(cnt)) : "memory")
#define MBARRIER_EXPECT_TX(addr, bytes) \
    asm volatile("mbarrier.arrive.expect_tx.shared.b64 _, [%0], %1;" \
                 :: "r"(addr), "r"((uint32_t)(bytes)) : "memory")
#define MBARRIER_WAIT_PARITY(addr, parity) do {                                   \
    uint32_t _m = (addr); uint32_t _p = (parity); uint32_t _done;                 \
    asm volatile("{\n\t.reg .pred p;\n\t"                                         \
        "mbarrier.try_wait.parity.acquire.cta.shared::cta.b64 p, [%1], %2;\n\t"   \
        "selp.b32 %0, 1, 0, p;\n\t}"                                              \
        : "=r"(_done) : "r"(_m), "r"(_p) : "memory");                             \
    if (!_done) {                                                                 \
        asm volatile("{\n\t.reg .pred P1;\n\t"                                    \
        "WL_%=:\n\t"                                                              \
        "mbarrier.try_wait.parity.acquire.cta.shared::cta.b64 P1, [%0], %1, 0x989680;\n\t" \
        "@P1 bra.uni WD_%=;\n\t"                                                  \
        "bra.uni WL_%=;\n\t"                                                      \
        "WD_%=:\n\t}"                                                             \
        :: "r"(_m), "r"(_p) : "memory");                                          \
    }                                                                             \
} while (0)
__device__ __forceinline__ void bulk_g2s(uint32_t dst, const void* src,
                                         uint32_t bytes, uint32_t mbar) {
    asm volatile(
        "cp.async.bulk.shared::cta.global.mbarrier::complete_tx::bytes [%0], [%1], %2, [%3];"
        :: "r"(dst), "l"(src), "r"(bytes), "r"(mbar) : "memory");
}

// ---------------------------------------------------------------------------
// 1) convx + count fused: count histogram + X -> {contiguous fp16, tiled fp16}
// ---------------------------------------------------------------------------
__global__ void __launch_bounds__(256) convx_count_kernel(
    const float* __restrict__ X,
    const int* __restrict__ ri_idx,
    const int* __restrict__ ro_idx)
{
    const int t = blockIdx.x * blockDim.x + threadIdx.x;
    if (t < BB * EE) {
        int b = t / EE;
        atomicAdd(&g_count[(2 * b + 0) * NN + ri_idx[t]], 1);
        atomicAdd(&g_count[(2 * b + 1) * NN + ro_idx[t]], 1);
    }
    // each iteration: 8 halves = (row r, chunk c), c in 0..31
    const size_t total = (size_t)RR * 32;
    const float4* src = reinterpret_cast<const float4*>(X);
    for (size_t i = (size_t)blockIdx.x * blockDim.x + threadIdx.x;
         i < total; i += (size_t)gridDim.x * blockDim.x) {
        int r = (int)(i >> 5);
        int c = (int)(i & 31);
        float4 f0 = src[2 * i];
        float4 f1 = src[2 * i + 1];
        uint2 o;
        o.x = pack_h2(f0.x, f0.y);
        o.y = pack_h2(f0.z, f0.w);
        uint2 o2;
        o2.x = pack_h2(f1.x, f1.y);
        o2.y = pack_h2(f1.z, f1.w);
        uint4 v = make_uint4(o.x, o.y, o2.x, o2.y);
        // contiguous copy (gather source)
        *reinterpret_cast<uint4*>(g_x_h + i * 8) = v;
        // tiled copy: kt = 32 + c/2, ko = 8*(c&1)
        size_t ta = ((size_t)(r >> 7) * 48 + 32 + (c >> 1)) * KT_STRIDE_H
                  + (size_t)(r & 127) * 24 + 8 * (c & 1);
        *reinterpret_cast<uint4*>(g_a_t + ta) = v;
    }
}

// ---------------------------------------------------------------------------
// 2) scan: decoupled lookback; re-zeros g_count
// ---------------------------------------------------------------------------
__global__ void __launch_bounds__(256) scan_kernel() {
    __shared__ int sh[256];
    __shared__ int s_off;
    const int bid = blockIdx.x;
    const int base = bid * SCAN_TILE + threadIdx.x * 8;

    int v[8]; int s = 0;
    #pragma unroll
    for (int j = 0; j < 8; j++) {
        int idx = base + j;
        int x = 0;
        if (idx < SEG) { x = g_count[idx]; g_count[idx] = 0; }
        v[j] = s;
        s += x;
    }
    sh[threadIdx.x] = s;
    __syncthreads();
    int acc = s;
    #pragma unroll
    for (int off = 1; off < 256; off <<= 1) {
        int t = (threadIdx.x >= off) ? sh[threadIdx.x - off] : 0;
        __syncthreads();
        acc += t;
        sh[threadIdx.x] = acc;
        __syncthreads();
    }
    const int excl_thread = acc - s;

    if (threadIdx.x == 255) {
        if (bid == 0) {
            g_scan_incl[0] = acc;
            __threadfence();
            g_scan_state[0] = 2;
            s_off = 0;
        } else {
            g_scan_agg[bid] = acc;
            __threadfence();
            g_scan_state[bid] = 1;
        }
    }
    if (bid > 0 && threadIdx.x == 0) {
        int off = 0;
        int j = bid - 1;
        while (true) {
            int st;
            do { st = g_scan_state[j]; } while (st == 0);
            __threadfence();
            if (st == 2) { off += g_scan_incl[j]; break; }
            off += g_scan_agg[j];
            j--;
        }
        s_off = off;
    }
    __syncthreads();
    const int off = s_off;
    if (bid > 0 && threadIdx.x == 255) {
        g_scan_incl[bid] = off + acc;
        __threadfence();
        g_scan_state[bid] = 2;
    }
    #pragma unroll
    for (int j = 0; j < 8; j++) {
        int idx = base + j;
        if (idx < SEG) g_start[idx] = off + excl_thread + v[j];
    }
}

// ---------------------------------------------------------------------------
// 3) fill CSR; resets scan flags
// ---------------------------------------------------------------------------
__global__ void fill_kernel(const float* __restrict__ e,
                            const int* __restrict__ ri_idx,
                            const int* __restrict__ ro_idx) {
    int t = blockIdx.x * blockDim.x + threadIdx.x;
    if (t < SCAN_NB) g_scan_state[t] = 0;
    if (t >= BB * EE) return;
    int b = t / EE;
    float w = e[t];
    int ri = ri_idx[t];
    int ro = ro_idx[t];
    int s0 = (2 * b + 0) * NN + ri;
    int s1 = (2 * b + 1) * NN + ro;
    int p0 = g_start[s0] + atomicAdd(&g_fill[s0], 1);
    g_entry[p0] = make_int2(ro, __float_as_int(w));
    int p1 = g_start[s1] + atomicAdd(&g_fill[s1], 1);
    g_entry[p1] = make_int2(ri, __float_as_int(w));
}

// ---------------------------------------------------------------------------
// 4) gather: reads contiguous fp16 X, writes TILED agg (kt = dir*16 + l/2)
// ---------------------------------------------------------------------------
__device__ __forceinline__ void fma8(float a[8], float w, const uint4& r) {
    const __half2* h = reinterpret_cast<const __half2*>(&r);
    #pragma unroll
    for (int i = 0; i < 4; i++) {
        float2 f = __half22float2(h[i]);
        a[2 * i]     = fmaf(w, f.x, a[2 * i]);
        a[2 * i + 1] = fmaf(w, f.y, a[2 * i + 1]);
    }
}

__global__ void __launch_bounds__(256) gather_kernel() {
    int wt = blockIdx.x * 8 + (threadIdx.x >> 5);
    if (wt >= SEG / 2) return;
    int lane = threadIdx.x & 31;
    int segA = wt * 2;
    int segB = segA + 1;

    int arrA = segA / NN, nA = segA - arrA * NN;
    int arrB = segB / NN, nB = segB - arrB * NN;

    int sA = g_start[segA];
    int sB = g_start[segB];
    int c = 0;
    if (lane < 2) { c = g_fill[segA + lane]; g_fill[segA + lane] = 0; }
    int cA = __shfl_sync(0xffffffffu, c, 0);
    int cB = __shfl_sync(0xffffffffu, c, 1);

    const uint4* XA = reinterpret_cast<const uint4*>(g_x_h + (size_t)(arrA >> 1) * NN * FF);
    const uint4* XB = reinterpret_cast<const uint4*>(g_x_h + (size_t)(arrB >> 1) * NN * FF);

    float aA[8] = {0.f, 0.f, 0.f, 0.f, 0.f, 0.f, 0.f, 0.f};
    float aB[8] = {0.f, 0.f, 0.f, 0.f, 0.f, 0.f, 0.f, 0.f};
    const uint4 z4 = make_uint4(0, 0, 0, 0);

    int iA = sA, eA = sA + cA;
    int iB = sB, eB = sB + cB;
    while (iA < eA || iB < eB) {
        bool pA0 = iA < eA,     pA1 = iA + 1 < eA;
        bool pB0 = iB < eB,     pB1 = iB + 1 < eB;
        int2 eA0 = make_int2(0, 0), eA1 = make_int2(0, 0);
        int2 eB0 = make_int2(0, 0), eB1 = make_int2(0, 0);
        if (pA0) eA0 = g_entry[iA];
        if (pA1) eA1 = g_entry[iA + 1];
        if (pB0) eB0 = g_entry[iB];
        if (pB1) eB1 = g_entry[iB + 1];

        uint4 rA0 = z4, rA1 = z4, rB0 = z4, rB1 = z4;
        if (pA0) rA0 = XA[(size_t)eA0.x * 32 + lane];
        if (pA1) rA1 = XA[(size_t)eA1.x * 32 + lane];
        if (pB0) rB0 = XB[(size_t)eB0.x * 32 + lane];
        if (pB1) rB1 = XB[(size_t)eB1.x * 32 + lane];

        fma8(aA, pA0 ? __int_as_float(eA0.y) : 0.f, rA0);
        fma8(aA, pA1 ? __int_as_float(eA1.y) : 0.f, rA1);
        fma8(aB, pB0 ? __int_as_float(eB0.y) : 0.f, rB0);
        fma8(aB, pB1 ? __int_as_float(eB1.y) : 0.f, rB1);
        iA += 2; iB += 2;
    }

    uint4 oA, oB;
    oA.x = pack_h2(aA[0], aA[1]); oA.y = pack_h2(aA[2], aA[3]);
    oA.z = pack_h2(aA[4], aA[5]); oA.w = pack_h2(aA[6], aA[7]);
    oB.x = pack_h2(aB[0], aB[1]); oB.y = pack_h2(aB[2], aB[3]);
    oB.z = pack_h2(aB[4], aB[5]); oB.w = pack_h2(aB[6], aB[7]);

    // tiled store: row r, dir d, lane l owns halves k = d*256 + 8l..8l+7
    // -> kt = d*16 + l/2, ko = 8*(l&1)
    const int klo = (lane >> 1);
    const int koff = 8 * (lane & 1);
    {
        int r = (arrA >> 1) * NN + nA, d = arrA & 1;
        size_t ta = ((size_t)(r >> 7) * 48 + d * 16 + klo) * KT_STRIDE_H
                  + (size_t)(r & 127) * 24 + koff;
        *reinterpret_cast<uint4*>(g_a_t + ta) = oA;
    }
    {
        int r = (arrB >> 1) * NN + nB, d = arrB & 1;
        size_t ta = ((size_t)(r >> 7) * 48 + d * 16 + klo) * KT_STRIDE_H
                  + (size_t)(r & 127) * 24 + koff;
        *reinterpret_cast<uint4*>(g_a_t + ta) = oB;
    }
}

// ---------------------------------------------------------------------------
// 5/6) pack W[K][N] fp32 -> fragment bricks fp16 (unchanged from R10)
// ---------------------------------------------------------------------------
__global__ void convw_pack_kernel(const float* __restrict__ W, __half* __restrict__ out,
                                  int K, int N) {
    int idx = blockIdx.x * blockDim.x + threadIdx.x;
    int nkb = K / 16;
    int total = (N / 8) * nkb * 32;
    if (idx >= total) return;
    int lane = idx & 31;
    int brick = idx >> 5;
    int nb = brick / nkb;
    int kb = brick - nb * nkb;
    int g = lane >> 2, tg = lane & 3;
    int n = nb * 8 + g;
    int k0 = kb * 16 + 2 * tg;
    __half h[4];
    h[0] = __float2half_rn(W[(size_t)(k0    ) * N + n]);
    h[1] = __float2half_rn(W[(size_t)(k0 + 1) * N + n]);
    h[2] = __float2half_rn(W[(size_t)(k0 + 8) * N + n]);
    h[3] = __float2half_rn(W[(size_t)(k0 + 9) * N + n]);
    *reinterpret_cast<uint2*>(out + (size_t)idx * 4) = *reinterpret_cast<uint2*>(h);
}

// ---------------------------------------------------------------------------
// 7) Fused 2-layer MLP, fp16 m16n8k16, 512 threads.
// Phase-1 A: tiled panels, ONE cp.async.bulk (6144 B) per stage, mbarrier-paced
// 4-deep ring. B: direct LDG.64 from fragment-packed W. Phase 2: Cs smem.
// smem: [0,64) mbarriers | 4 x 6144 A stages | Cs 128x280 halves.
// ---------------------------------------------------------------------------
#define GBM 128
#define NST 4
#define A_STG_B 6144
#define C_LDH 280
#define MB_OFF  0
#define AST_OFF 64
#define CS_OFF  (AST_OFF + NST * A_STG_B)                 // 24640
#define SMEM_BYTES (CS_OFF + GBM * C_LDH * 2)             // 96320

#define NT1 NKB1            // 48
#define NT2 NKB2            // 16

__global__ void __launch_bounds__(512, 1) fused_mlp_kernel(
    const float* __restrict__ b1,
    const float* __restrict__ b2,
    float* __restrict__ Out,
    int rows)
{
    extern __shared__ char smem[];
    const uint32_t smem_u = (uint32_t)__cvta_generic_to_shared(smem);
    const uint32_t* Asw = reinterpret_cast<const uint32_t*>(smem + AST_OFF);
    uint32_t* Csw = reinterpret_cast<uint32_t*>(smem + CS_OFF);

    const int tid  = threadIdx.x;
    const int warp = tid >> 5;
    const int lane = tid & 31;
    const int g    = lane >> 2;
    const int tg   = lane & 3;
    const int wm   = warp & 3;         // M group (32 rows)
    const int wn   = warp >> 2;        // N group (64 cols)
    const int rowBase = blockIdx.x * GBM;
    const __half* panel = g_a_t + (size_t)blockIdx.x * PANEL_H;

    // per-warp base pointers into fragment-packed W
    const uint2* w1b = reinterpret_cast<const uint2*>(g_w1p) + ((size_t)(wn * 8) * NT1) * 32 + lane;
    const uint2* w2b = reinterpret_cast<const uint2*>(g_w2p) + ((size_t)(wn * 8) * NT2) * 32 + lane;

    float acc[2][8][4];
    #pragma unroll
    for (int mt = 0; mt < 2; mt++)
        #pragma unroll
        for (int nt = 0; nt < 8; nt++)
            #pragma unroll
            for (int r = 0; r < 4; r++) acc[mt][nt][r] = 0.f;

    // ---- init mbarriers + prologue bulk loads ----
    if (tid == 0) {
        #pragma unroll
        for (int s = 0; s < NST; s++) MBARRIER_INIT(smem_u + MB_OFF + s * 8, 1);
        asm volatile("fence.proxy.async.shared::cta;" ::: "memory");
        #pragma unroll
        for (int s = 0; s < NST - 1; s++) {
            MBARRIER_EXPECT_TX(smem_u + MB_OFF + s * 8, A_STG_B);
            bulk_g2s(smem_u + AST_OFF + s * A_STG_B,
                     panel + (size_t)s * KT_STRIDE_H, A_STG_B,
                     smem_u + MB_OFF + s * 8);
        }
    }
    __syncthreads();

    // ================= Phase 1: K = 768, [agg|X] @ W1 =================
    for (int t = 0; t < NT1; t++) {
        // B fragments for this tile (overlap with mbarrier wait)
        uint2 bfr[8];
        #pragma unroll
        for (int nt = 0; nt < 8; nt++)
            bfr[nt] = w1b[(size_t)(nt * NT1 + t) * 32];

        const int st = t & (NST - 1);
        MBARRIER_WAIT_PARITY(smem_u + MB_OFF + st * 8, (uint32_t)((t >> 2) & 1));
        __syncthreads();   // all warps done reading stage (t-1)&3 -> safe to refill

        if (tid == 0) {
            const int tn = t + NST - 1;
            if (tn < NT1) {
                const int sn = tn & (NST - 1);
                MBARRIER_EXPECT_TX(smem_u + MB_OFF + sn * 8, A_STG_B);
                bulk_g2s(smem_u + AST_OFF + sn * A_STG_B,
                         panel + (size_t)tn * KT_STRIDE_H, A_STG_B,
                         smem_u + MB_OFF + sn * 8);
            }
        }

        const uint32_t* Aw = Asw + st * (A_STG_B / 4);
        uint32_t a[2][4];
        #pragma unroll
        for (int mt = 0; mt < 2; mt++) {
            const int r = wm * 32 + mt * 16 + g;
            a[mt][0] = Aw[(r    ) * 12 + tg    ];
            a[mt][1] = Aw[(r + 8) * 12 + tg    ];
            a[mt][2] = Aw[(r    ) * 12 + tg + 4];
            a[mt][3] = Aw[(r + 8) * 12 + tg + 4];
        }
        #pragma unroll
        for (int mt = 0; mt < 2; mt++)
            #pragma unroll
            for (int nt = 0; nt < 8; nt++)
                mma_f16(acc[mt][nt], a[mt][0], a[mt][1], a[mt][2], a[mt][3],
                        bfr[nt].x, bfr[nt].y);
    }

    // ---- epilogue 1: bias + tanh -> Cs fp16 ----
    __syncthreads();
    #pragma unroll
    for (int mt = 0; mt < 2; mt++) {
        const int r0 = wm * 32 + mt * 16 + g;
        #pragma unroll
        for (int nt = 0; nt < 8; nt++) {
            const int col = wn * 64 + nt * 8 + tg * 2;
            const float bb0 = b1[col];
            const float bb1 = b1[col + 1];
            Csw[(r0    ) * 140 + (col >> 1)] =
                pack_h2(tanh_approx(acc[mt][nt][0] + bb0),
                        tanh_approx(acc[mt][nt][1] + bb1));
            Csw[(r0 + 8) * 140 + (col >> 1)] =
                pack_h2(tanh_approx(acc[mt][nt][2] + bb0),
                        tanh_approx(acc[mt][nt][3] + bb1));
            acc[mt][nt][0] = 0.f; acc[mt][nt][1] = 0.f;
            acc[mt][nt][2] = 0.f; acc[mt][nt][3] = 0.f;
        }
    }
    __syncthreads();

    // ================= Phase 2: K = 256, Cs @ W2 =================
    for (int t = 0; t < NT2; t++) {
        uint2 bfr[8];
        #pragma unroll
        for (int nt = 0; nt < 8; nt++)
            bfr[nt] = w2b[(size_t)(nt * NT2 + t) * 32];

        const int kw = t * 8;
        uint32_t a[2][4];
        #pragma unroll
        for (int mt = 0; mt < 2; mt++) {
            const int r = wm * 32 + mt * 16 + g;
            a[mt][0] = Csw[(r    ) * 140 + kw + tg    ];
            a[mt][1] = Csw[(r + 8) * 140 + kw + tg    ];
            a[mt][2] = Csw[(r    ) * 140 + kw + tg + 4];
            a[mt][3] = Csw[(r + 8) * 140 + kw + tg + 4];
        }
        #pragma unroll
        for (int mt = 0; mt < 2; mt++)
            #pragma unroll
            for (int nt = 0; nt < 8; nt++)
                mma_f16(acc[mt][nt], a[mt][0], a[mt][1], a[mt][2], a[mt][3],
                        bfr[nt].x, bfr[nt].y);
    }

    // ---- epilogue 2: bias + tanh -> global fp32 ----
    #pragma unroll
    for (int mt = 0; mt < 2; mt++) {
        const int r0 = rowBase + wm * 32 + mt * 16 + g;
        #pragma unroll
        for (int nt = 0; nt < 8; nt++) {
            const int col = wn * 64 + nt * 8 + tg * 2;
            const float bb0 = b2[col];
            const float bb1 = b2[col + 1];
            if (r0 < rows) {
                float2 v;
                v.x = tanh_approx(acc[mt][nt][0] + bb0);
                v.y = tanh_approx(acc[mt][nt][1] + bb1);
                *reinterpret_cast<float2*>(Out + (size_t)r0 * 256 + col) = v;
            }
            if (r0 + 8 < rows) {
                float2 v;
                v.x = tanh_approx(acc[mt][nt][2] + bb0);
                v.y = tanh_approx(acc[mt][nt][3] + bb1);
                *reinterpret_cast<float2*>(Out + (size_t)(r0 + 8) * 256 + col) = v;
            }
        }
    }
}

// ---------------------------------------------------------------------------
// Launcher. Inputs (metadata order): X, e, ri_idx, ro_idx, W1, b1, W2, b2
// ---------------------------------------------------------------------------
extern "C" void kernel_launch(void* const* d_in, const int* in_sizes, int n_in,
                              void* d_out, int out_size)
{
    (void)in_sizes; (void)n_in; (void)out_size;

    const float* X  = (const float*)d_in[0];
    const float* e  = (const float*)d_in[1];
    const int*   ri = (const int*)  d_in[2];
    const int*   ro = (const int*)  d_in[3];
    const float* W1 = (const float*)d_in[4];
    const float* b1 = (const float*)d_in[5];
    const float* W2 = (const float*)d_in[6];
    const float* b2 = (const float*)d_in[7];
    float* out = (float*)d_out;

    __half *w1p_ptr = nullptr, *w2p_ptr = nullptr;
    cudaGetSymbolAddress((void**)&w1p_ptr, g_w1p);
    cudaGetSymbolAddress((void**)&w2p_ptr, g_w2p);

    cudaFuncSetAttribute(fused_mlp_kernel,
                         cudaFuncAttributeMaxDynamicSharedMemorySize, SMEM_BYTES);

    // 1: convx+count, 2: scan, 3: fill, 4: gather (profiled)
    convx_count_kernel<<<(BB * EE + 255) / 256, 256>>>(X, ri, ro);
    scan_kernel<<<SCAN_NB, 256>>>();
    fill_kernel<<<(BB * EE + 255) / 256, 256>>>(e, ri, ro);
    gather_kernel<<<(SEG / 2) / 8, 256>>>();

    // 5/6: weight fragment packing
    convw_pack_kernel<<<(32 * NKB1 * 32 + 255) / 256, 256>>>(W1, w1p_ptr, KTOT, 256);
    convw_pack_kernel<<<(32 * NKB2 * 32 + 255) / 256, 256>>>(W2, w2p_ptr, 256, 256);

    // 7: fused MLP
    fused_mlp_kernel<<<NBLK, 512, SMEM_BYTES>>>(b1, b2, out, RR);
}

// round 12
// speedup vs baseline: 1.0317x; 1.0317x over previous
#include <cuda_runtime.h>
#include <cuda_fp16.h>
#include <cstdint>
#include <cstddef>

// Problem constants (fixed by the reference)
#define BB   2
#define NN   50000
#define EE   150000
#define FF   256
#define OUTD 256
#define RR   (BB * NN)       // 100000 rows
#define KTOT (3 * FF)        // 768
#define SEG  (4 * NN)        // 200000 segments
#define TOTE (4 * EE)        // 600000 CSR entries

#define NKB1 (KTOT / 16)     // 48 k-bricks for W1
#define NKB2 (256 / 16)      // 16 k-bricks for W2

// fp16 operand buffers
__device__ __half g_agg_h[(size_t)RR * 512];   // [r][0:256]=mi, [r][256:512]=mo
__device__ __half g_x_h[(size_t)RR * 256];     // X in fp16
// Fragment-packed weights: brick (nb, kb) = 32 lanes x 4 halves (8B/lane).
__device__ __half g_w1p[32 * NKB1 * 128];
__device__ __half g_w2p[32 * NKB2 * 128];

// CSR scratch (self-cleaning across calls)
__device__ int   g_count[SEG];
__device__ int   g_fill[SEG];
__device__ int   g_start[SEG];
__device__ int2  g_entry[TOTE];                // .x = src node, .y = weight bits

#define SCAN_TILE 2048
#define SCAN_NB   ((SEG + SCAN_TILE - 1) / SCAN_TILE)   // 98
__device__ volatile int g_scan_state[SCAN_NB];
__device__ int g_scan_agg[SCAN_NB];
__device__ int g_scan_incl[SCAN_NB];

// ---------------------------------------------------------------------------
// helpers
// ---------------------------------------------------------------------------
__device__ __forceinline__ float tanh_approx(float x) {
    float y;
    asm("tanh.approx.f32 %0, %1;" : "=f"(y) : "f"(x));
    return y;
}
__device__ __forceinline__ void cp16(uint32_t dst, const void* src, int bytes) {
    asm volatile("cp.async.cg.shared.global [%0], [%1], 16, %2;"
                 :: "r"(dst), "l"(src), "r"(bytes));
}
__device__ __forceinline__ uint32_t pack_h2(float lo, float hi) {
    __half2 h = __floats2half2_rn(lo, hi);
    return *reinterpret_cast<uint32_t*>(&h);
}
__device__ __forceinline__ void mma_f16(float c[4],
                                        uint32_t a0, uint32_t a1, uint32_t a2, uint32_t a3,
                                        uint32_t b0, uint32_t b1) {
    asm volatile(
        "mma.sync.aligned.m16n8k16.row.col.f32.f16.f16.f32 "
        "{%0,%1,%2,%3}, {%4,%5,%6,%7}, {%8,%9}, {%0,%1,%2,%3};"
        : "+f"(c[0]), "+f"(c[1]), "+f"(c[2]), "+f"(c[3])
        : "r"(a0), "r"(a1), "r"(a2), "r"(a3), "r"(b0), "r"(b1));
}

// ---------------------------------------------------------------------------
// 1) convx + count fused
// ---------------------------------------------------------------------------
__global__ void __launch_bounds__(256) convx_count_kernel(
    const float* __restrict__ X,
    const int* __restrict__ ri_idx,
    const int* __restrict__ ro_idx)
{
    const int t = blockIdx.x * blockDim.x + threadIdx.x;
    if (t < BB * EE) {
        int b = t / EE;
        atomicAdd(&g_count[(2 * b + 0) * NN + ri_idx[t]], 1);
        atomicAdd(&g_count[(2 * b + 1) * NN + ro_idx[t]], 1);
    }
    const size_t total = (size_t)RR * 256 / 8;
    uint4* dst = reinterpret_cast<uint4*>(g_x_h);
    const float4* src = reinterpret_cast<const float4*>(X);
    for (size_t i = (size_t)blockIdx.x * blockDim.x + threadIdx.x;
         i < total; i += (size_t)gridDim.x * blockDim.x) {
        float4 f0 = src[2 * i];
        float4 f1 = src[2 * i + 1];
        uint4 o;
        o.x = pack_h2(f0.x, f0.y); o.y = pack_h2(f0.z, f0.w);
        o.z = pack_h2(f1.x, f1.y); o.w = pack_h2(f1.z, f1.w);
        dst[i] = o;
    }
}

// ---------------------------------------------------------------------------
// 2) scan: decoupled lookback; re-zeros g_count
// ---------------------------------------------------------------------------
__global__ void __launch_bounds__(256) scan_kernel() {
    __shared__ int sh[256];
    __shared__ int s_off;
    const int bid = blockIdx.x;
    const int base = bid * SCAN_TILE + threadIdx.x * 8;

    int v[8]; int s = 0;
    #pragma unroll
    for (int j = 0; j < 8; j++) {
        int idx = base + j;
        int x = 0;
        if (idx < SEG) { x = g_count[idx]; g_count[idx] = 0; }
        v[j] = s;
        s += x;
    }
    sh[threadIdx.x] = s;
    __syncthreads();
    int acc = s;
    #pragma unroll
    for (int off = 1; off < 256; off <<= 1) {
        int t = (threadIdx.x >= off) ? sh[threadIdx.x - off] : 0;
        __syncthreads();
        acc += t;
        sh[threadIdx.x] = acc;
        __syncthreads();
    }
    const int excl_thread = acc - s;

    if (threadIdx.x == 255) {
        if (bid == 0) {
            g_scan_incl[0] = acc;
            __threadfence();
            g_scan_state[0] = 2;
            s_off = 0;
        } else {
            g_scan_agg[bid] = acc;
            __threadfence();
            g_scan_state[bid] = 1;
        }
    }
    if (bid > 0 && threadIdx.x == 0) {
        int off = 0;
        int j = bid - 1;
        while (true) {
            int st;
            do { st = g_scan_state[j]; } while (st == 0);
            __threadfence();
            if (st == 2) { off += g_scan_incl[j]; break; }
            off += g_scan_agg[j];
            j--;
        }
        s_off = off;
    }
    __syncthreads();
    const int off = s_off;
    if (bid > 0 && threadIdx.x == 255) {
        g_scan_incl[bid] = off + acc;
        __threadfence();
        g_scan_state[bid] = 2;
    }
    #pragma unroll
    for (int j = 0; j < 8; j++) {
        int idx = base + j;
        if (idx < SEG) g_start[idx] = off + excl_thread + v[j];
    }
}

// ---------------------------------------------------------------------------
// 3) fill CSR; resets scan flags
// ---------------------------------------------------------------------------
__global__ void fill_kernel(const float* __restrict__ e,
                            const int* __restrict__ ri_idx,
                            const int* __restrict__ ro_idx) {
    int t = blockIdx.x * blockDim.x + threadIdx.x;
    if (t < SCAN_NB) g_scan_state[t] = 0;
    if (t >= BB * EE) return;
    int b = t / EE;
    float w = e[t];
    int ri = ri_idx[t];
    int ro = ro_idx[t];
    int s0 = (2 * b + 0) * NN + ri;
    int s1 = (2 * b + 1) * NN + ro;
    int p0 = g_start[s0] + atomicAdd(&g_fill[s0], 1);
    g_entry[p0] = make_int2(ro, __float_as_int(w));
    int p1 = g_start[s1] + atomicAdd(&g_fill[s1], 1);
    g_entry[p1] = make_int2(ri, __float_as_int(w));
}

// ---------------------------------------------------------------------------
// 4) gather on fp16 X: one warp per FOUR segments (4 independent CSR chains,
// unroll-2 each => up to 8 row-loads + 8 entry-loads in flight).
// NN % 4 == 0 => a warp's 4 segments share the same (b, dir) array.
// Row = 256 halves = 512B = ONE uint4 per lane. fp32 accumulate.
// ---------------------------------------------------------------------------
__device__ __forceinline__ void fma8(float a[8], float w, const uint4& r) {
    const __half2* h = reinterpret_cast<const __half2*>(&r);
    #pragma unroll
    for (int i = 0; i < 4; i++) {
        float2 f = __half22float2(h[i]);
        a[2 * i]     = fmaf(w, f.x, a[2 * i]);
        a[2 * i + 1] = fmaf(w, f.y, a[2 * i + 1]);
    }
}

__global__ void __launch_bounds__(256) gather_kernel() {
    int wt = blockIdx.x * 8 + (threadIdx.x >> 5);
    if (wt >= SEG / 4) return;
    int lane = threadIdx.x & 31;

    const int seg0 = wt * 4;
    const int arr  = seg0 / NN;          // all 4 segments in same arr
    const int n0   = seg0 - arr * NN;
    const int b    = arr >> 1;
    const int dir  = arr & 1;

    int cval = 0;
    if (lane < 4) { cval = g_fill[seg0 + lane]; g_fill[seg0 + lane] = 0; }

    int i[4], e[4];
    #pragma unroll
    for (int j = 0; j < 4; j++) {
        int c = __shfl_sync(0xffffffffu, cval, j);
        i[j] = g_start[seg0 + j];
        e[j] = i[j] + c;
    }

    const uint4* Xb = reinterpret_cast<const uint4*>(g_x_h + (size_t)b * NN * FF);
    float acc[4][8];
    #pragma unroll
    for (int j = 0; j < 4; j++)
        #pragma unroll
        for (int q = 0; q < 8; q++) acc[j][q] = 0.f;

    const uint4 z4 = make_uint4(0, 0, 0, 0);

    while (i[0] < e[0] || i[1] < e[1] || i[2] < e[2] || i[3] < e[3]) {
        bool p0[4], p1[4];
        int2 en0[4], en1[4];
        #pragma unroll
        for (int j = 0; j < 4; j++) {
            p0[j] = i[j] < e[j];
            p1[j] = i[j] + 1 < e[j];
            en0[j] = make_int2(0, 0);
            en1[j] = make_int2(0, 0);
            if (p0[j]) en0[j] = g_entry[i[j]];
            if (p1[j]) en1[j] = g_entry[i[j] + 1];
        }
        uint4 r0[4], r1[4];
        #pragma unroll
        for (int j = 0; j < 4; j++) {
            r0[j] = z4; r1[j] = z4;
            if (p0[j]) r0[j] = Xb[(size_t)en0[j].x * 32 + lane];
            if (p1[j]) r1[j] = Xb[(size_t)en1[j].x * 32 + lane];
        }
        #pragma unroll
        for (int j = 0; j < 4; j++) {
            fma8(acc[j], p0[j] ? __int_as_float(en0[j].y) : 0.f, r0[j]);
            fma8(acc[j], p1[j] ? __int_as_float(en1[j].y) : 0.f, r1[j]);
            i[j] += 2;
        }
    }

    #pragma unroll
    for (int j = 0; j < 4; j++) {
        uint4 o;
        o.x = pack_h2(acc[j][0], acc[j][1]);
        o.y = pack_h2(acc[j][2], acc[j][3]);
        o.z = pack_h2(acc[j][4], acc[j][5]);
        o.w = pack_h2(acc[j][6], acc[j][7]);
        __half* d = g_agg_h + ((size_t)b * NN + n0 + j) * 512 + dir * 256;
        *reinterpret_cast<uint4*>(d + 8 * lane) = o;
    }
}

// ---------------------------------------------------------------------------
// 5/6) pack W[K][N] fp32 -> fragment bricks fp16
// ---------------------------------------------------------------------------
__global__ void convw_pack_kernel(const float* __restrict__ W, __half* __restrict__ out,
                                  int K, int N) {
    int idx = blockIdx.x * blockDim.x + threadIdx.x;
    int nkb = K / 16;
    int total = (N / 8) * nkb * 32;
    if (idx >= total) return;
    int lane = idx & 31;
    int brick = idx >> 5;
    int nb = brick / nkb;
    int kb = brick - nb * nkb;
    int g = lane >> 2, tg = lane & 3;
    int n = nb * 8 + g;
    int k0 = kb * 16 + 2 * tg;
    __half h[4];
    h[0] = __float2half_rn(W[(size_t)(k0    ) * N + n]);
    h[1] = __float2half_rn(W[(size_t)(k0 + 1) * N + n]);
    h[2] = __float2half_rn(W[(size_t)(k0 + 8) * N + n]);
    h[3] = __float2half_rn(W[(size_t)(k0 + 9) * N + n]);
    *reinterpret_cast<uint2*>(out + (size_t)idx * 4) = *reinterpret_cast<uint2*>(h);
}

// ---------------------------------------------------------------------------
// 7) Fused 2-layer MLP (R10, unchanged): fp16 m16n8k16, 512 threads.
// A via 4-stage cp.async smem; B fragments via direct LDG.64 from L2.
// ---------------------------------------------------------------------------
#define GBM 128
#define GBK 16
#define NST 4
#define A_LDH 24
#define C_LDH 280
#define A_STG_B (GBM * A_LDH * 2)                 // 6144 B
#define CS_OFF  (NST * A_STG_B)                   // 24576
#define SMEM_BYTES (CS_OFF + GBM * C_LDH * 2)     // 96256

#define NT1 NKB1            // 48
#define NT2 NKB2            // 16

__global__ void __launch_bounds__(512, 1) fused_mlp_kernel(
    const float* __restrict__ b1,
    const float* __restrict__ b2,
    float* __restrict__ Out,
    int rows)
{
    extern __shared__ char smem[];
    const uint32_t smem_u = (uint32_t)__cvta_generic_to_shared(smem);
    const uint32_t* Asw = reinterpret_cast<const uint32_t*>(smem);
    uint32_t* Csw = reinterpret_cast<uint32_t*>(smem + CS_OFF);

    const int tid  = threadIdx.x;
    const int warp = tid >> 5;
    const int lane = tid & 31;
    const int g    = lane >> 2;
    const int tg   = lane & 3;
    const int wm   = warp & 3;
    const int wn   = warp >> 2;
    const int rowBase = blockIdx.x * GBM;

    const uint2* w1b = reinterpret_cast<const uint2*>(g_w1p) + ((size_t)(wn * 8) * NT1) * 32 + lane;
    const uint2* w2b = reinterpret_cast<const uint2*>(g_w2p) + ((size_t)(wn * 8) * NT2) * 32 + lane;

    float acc[2][8][4];
    #pragma unroll
    for (int mt = 0; mt < 2; mt++)
        #pragma unroll
        for (int nt = 0; nt < 8; nt++)
            #pragma unroll
            for (int r = 0; r < 4; r++) acc[mt][nt][r] = 0.f;

    auto load_tileA = [&](int st, int t) {
        if (tid < 256) {
            const int k0 = t * GBK;
            const int row = tid >> 1;
            const int kc  = (tid & 1) * 8;
            const int gr  = rowBase + row;
            const __half* asrc = (k0 < 512)
                ? g_agg_h + (size_t)gr * 512 + (k0 + kc)
                : g_x_h   + (size_t)gr * 256 + (k0 - 512 + kc);
            cp16(smem_u + (uint32_t)(st * A_STG_B + (row * A_LDH + kc) * 2),
                 asrc, gr < rows ? 16 : 0);
        }
    };

    #pragma unroll
    for (int t = 0; t < NST - 1; t++) {
        load_tileA(t, t);
        asm volatile("cp.async.commit_group;");
    }

    for (int t = 0; t < NT1; t++) {
        uint2 bfr[8];
        #pragma unroll
        for (int nt = 0; nt < 8; nt++)
            bfr[nt] = w1b[(size_t)(nt * NT1 + t) * 32];

        asm volatile("cp.async.wait_group %0;" :: "n"(NST - 2));
        __syncthreads();
        const int st = t & (NST - 1);
        {
            const int tn = t + NST - 1;
            if (tn < NT1) load_tileA(tn & (NST - 1), tn);
            asm volatile("cp.async.commit_group;");
        }
        const uint32_t* Aw = Asw + st * (A_STG_B / 4);

        uint32_t a[2][4];
        #pragma unroll
        for (int mt = 0; mt < 2; mt++) {
            const int r = wm * 32 + mt * 16 + g;
            a[mt][0] = Aw[(r    ) * 12 + tg    ];
            a[mt][1] = Aw[(r + 8) * 12 + tg    ];
            a[mt][2] = Aw[(r    ) * 12 + tg + 4];
            a[mt][3] = Aw[(r + 8) * 12 + tg + 4];
        }
        #pragma unroll
        for (int mt = 0; mt < 2; mt++)
            #pragma unroll
            for (int nt = 0; nt < 8; nt++)
                mma_f16(acc[mt][nt], a[mt][0], a[mt][1], a[mt][2], a[mt][3],
                        bfr[nt].x, bfr[nt].y);
    }

    __syncthreads();
    #pragma unroll
    for (int mt = 0; mt < 2; mt++) {
        const int r0 = wm * 32 + mt * 16 + g;
        #pragma unroll
        for (int nt = 0; nt < 8; nt++) {
            const int col = wn * 64 + nt * 8 + tg * 2;
            const float bb0 = b1[col];
            const float bb1 = b1[col + 1];
            Csw[(r0    ) * 140 + (col >> 1)] =
                pack_h2(tanh_approx(acc[mt][nt][0] + bb0),
                        tanh_approx(acc[mt][nt][1] + bb1));
            Csw[(r0 + 8) * 140 + (col >> 1)] =
                pack_h2(tanh_approx(acc[mt][nt][2] + bb0),
                        tanh_approx(acc[mt][nt][3] + bb1));
            acc[mt][nt][0] = 0.f; acc[mt][nt][1] = 0.f;
            acc[mt][nt][2] = 0.f; acc[mt][nt][3] = 0.f;
        }
    }
    __syncthreads();

    for (int t = 0; t < NT2; t++) {
        uint2 bfr[8];
        #pragma unroll
        for (int nt = 0; nt < 8; nt++)
            bfr[nt] = w2b[(size_t)(nt * NT2 + t) * 32];

        const int kw = t * 8;
        uint32_t a[2][4];
        #pragma unroll
        for (int mt = 0; mt < 2; mt++) {
            const int r = wm * 32 + mt * 16 + g;
            a[mt][0] = Csw[(r    ) * 140 + kw + tg    ];
            a[mt][1] = Csw[(r + 8) * 140 + kw + tg    ];
            a[mt][2] = Csw[(r    ) * 140 + kw + tg + 4];
            a[mt][3] = Csw[(r + 8) * 140 + kw + tg + 4];
        }
        #pragma unroll
        for (int mt = 0; mt < 2; mt++)
            #pragma unroll
            for (int nt = 0; nt < 8; nt++)
                mma_f16(acc[mt][nt], a[mt][0], a[mt][1], a[mt][2], a[mt][3],
                        bfr[nt].x, bfr[nt].y);
    }

    #pragma unroll
    for (int mt = 0; mt < 2; mt++) {
        const int r0 = rowBase + wm * 32 + mt * 16 + g;
        #pragma unroll
        for (int nt = 0; nt < 8; nt++) {
            const int col = wn * 64 + nt * 8 + tg * 2;
            const float bb0 = b2[col];
            const float bb1 = b2[col + 1];
            if (r0 < rows) {
                float2 v;
                v.x = tanh_approx(acc[mt][nt][0] + bb0);
                v.y = tanh_approx(acc[mt][nt][1] + bb1);
                *reinterpret_cast<float2*>(Out + (size_t)r0 * 256 + col) = v;
            }
            if (r0 + 8 < rows) {
                float2 v;
                v.x = tanh_approx(acc[mt][nt][2] + bb0);
                v.y = tanh_approx(acc[mt][nt][3] + bb1);
                *reinterpret_cast<float2*>(Out + (size_t)(r0 + 8) * 256 + col) = v;
            }
        }
    }
}

// ---------------------------------------------------------------------------
// Launcher. Inputs (metadata order): X, e, ri_idx, ro_idx, W1, b1, W2, b2
// ---------------------------------------------------------------------------
extern "C" void kernel_launch(void* const* d_in, const int* in_sizes, int n_in,
                              void* d_out, int out_size)
{
    (void)in_sizes; (void)n_in; (void)out_size;

    const float* X  = (const float*)d_in[0];
    const float* e  = (const float*)d_in[1];
    const int*   ri = (const int*)  d_in[2];
    const int*   ro = (const int*)  d_in[3];
    const float* W1 = (const float*)d_in[4];
    const float* b1 = (const float*)d_in[5];
    const float* W2 = (const float*)d_in[6];
    const float* b2 = (const float*)d_in[7];
    float* out = (float*)d_out;

    __half *w1p_ptr = nullptr, *w2p_ptr = nullptr;
    cudaGetSymbolAddress((void**)&w1p_ptr, g_w1p);
    cudaGetSymbolAddress((void**)&w2p_ptr, g_w2p);

    cudaFuncSetAttribute(fused_mlp_kernel,
                         cudaFuncAttributeMaxDynamicSharedMemorySize, SMEM_BYTES);

    // 1: convx+count, 2: scan, 3: fill, 4: gather (profiled)
    convx_count_kernel<<<(BB * EE + 255) / 256, 256>>>(X, ri, ro);
    scan_kernel<<<SCAN_NB, 256>>>();
    fill_kernel<<<(BB * EE + 255) / 256, 256>>>(e, ri, ro);
    gather_kernel<<<(SEG / 4 + 7) / 8, 256>>>();

    // 5/6: weight fragment packing
    convw_pack_kernel<<<(32 * NKB1 * 32 + 255) / 256, 256>>>(W1, w1p_ptr, KTOT, 256);
    convw_pack_kernel<<<(32 * NKB2 * 32 + 255) / 256, 256>>>(W2, w2p_ptr, 256, 256);

    // 7: fused MLP
    const int nblk = (RR + GBM - 1) / GBM;    // 782
    fused_mlp_kernel<<<nblk, 512, SMEM_BYTES>>>(b1, b2, out, RR);
}